// round 2
// baseline (speedup 1.0000x reference)
#include <cuda_runtime.h>
#include <math.h>

#define NL 4
#define D 512
#define H 8
#define DFF 2048
#define T 256
#define B 8
#define NBUCK 33
#define DH 64
#define MTOK (B*T)   // 2048

// ---------------- scratch (device globals; no allocation allowed) ----------
__device__ float g_x[MTOK*D];
__device__ float g_h[MTOK*D];
__device__ float g_q[MTOK*D];
__device__ float g_k[MTOK*D];
__device__ float g_v[MTOK*D];
__device__ float g_ctx[MTOK*D];
__device__ float g_out[MTOK*D];
__device__ float g_hid[MTOK*DFF];
__device__ float g_srel[B*H*T*NBUCK];

// ---------------- reductions ----------------
__device__ __forceinline__ float blkSum(float v, float* sc) {
    __syncthreads();
    int tid = threadIdx.x, lane = tid & 31, w = tid >> 5, nw = blockDim.x >> 5;
    #pragma unroll
    for (int o = 16; o; o >>= 1) v += __shfl_xor_sync(0xffffffffu, v, o);
    if (lane == 0) sc[w] = v;
    __syncthreads();
    if (tid == 0) { float t = 0.f; for (int i = 0; i < nw; i++) t += sc[i]; sc[0] = t; }
    __syncthreads();
    return sc[0];
}
__device__ __forceinline__ float blkMax(float v, float* sc) {
    __syncthreads();
    int tid = threadIdx.x, lane = tid & 31, w = tid >> 5, nw = blockDim.x >> 5;
    #pragma unroll
    for (int o = 16; o; o >>= 1) v = fmaxf(v, __shfl_xor_sync(0xffffffffu, v, o));
    if (lane == 0) sc[w] = v;
    __syncthreads();
    if (tid == 0) { float t = -3.0e38f; for (int i = 0; i < nw; i++) t = fmaxf(t, sc[i]); sc[0] = t; }
    __syncthreads();
    return sc[0];
}

// ---------------- embedding: x = src*sqrt(D) + sinusoid PE, (T,B,D)->(B,T,D)
__global__ void embed_kernel(const float* __restrict__ src) {
    int i = blockIdx.x * blockDim.x + threadIdx.x;
    if (i >= MTOK * D) return;
    int d = i & (D - 1);
    int t = (i / D) & (T - 1);
    int b = i / (D * T);
    float ang = (float)t * expf(-(float)(d & ~1) * (logf(10000.0f) / (float)D));
    float pe = (d & 1) ? cosf(ang) : sinf(ang);
    g_x[i] = src[((t * B) + b) * D + d] * sqrtf((float)D) + pe;
}

// ---------------- layernorm (per token row of length D), 128 threads -------
__global__ __launch_bounds__(128) void ln_kernel(const float* __restrict__ in,
                                                 float* __restrict__ out,
                                                 const float* __restrict__ gam,
                                                 const float* __restrict__ bet) {
    __shared__ float sc[32];
    int tok = blockIdx.x;
    int tid = threadIdx.x;
    const float4 vv = ((const float4*)(in + tok * D))[tid];
    float s = vv.x + vv.y + vv.z + vv.w;
    float mean = blkSum(s, sc) * (1.0f / D);
    float dx = vv.x - mean, dy = vv.y - mean, dz = vv.z - mean, dw = vv.w - mean;
    float sq = dx * dx + dy * dy + dz * dz + dw * dw;
    float var = blkSum(sq, sc) * (1.0f / D);
    float inv = rsqrtf(var + 1e-6f);
    float4 gv = ((const float4*)gam)[tid];
    float4 bv = ((const float4*)bet)[tid];
    float4 o;
    o.x = dx * inv * gv.x + bv.x;
    o.y = dy * inv * gv.y + bv.y;
    o.z = dz * inv * gv.z + bv.z;
    o.w = dw * inv * gv.w + bv.w;
    ((float4*)(out + tok * D))[tid] = o;
}

// ---------------- GEMM: C[M,N] = scale*(A[M,K] @ W[N,K]^T + bias) (+relu)(+resid)
__global__ __launch_bounds__(256) void gemm_kernel(
    const float* __restrict__ A, const float* __restrict__ W,
    const float* __restrict__ bias, const float* __restrict__ resid,
    float* __restrict__ C, int M, int N, int K, float scale, int relu)
{
    __shared__ float As[16][64];
    __shared__ float Ws[16][64];
    int tid = threadIdx.x;
    int tx = tid & 15, ty = tid >> 4;
    int m0 = blockIdx.y << 6, n0 = blockIdx.x << 6;
    int r = tid >> 2, c4 = (tid & 3) << 2;
    float acc[4][4];
    #pragma unroll
    for (int i = 0; i < 4; i++)
        #pragma unroll
        for (int j = 0; j < 4; j++) acc[i][j] = 0.f;
    const float* Aptr = A + (size_t)(m0 + r) * K + c4;
    const float* Wptr = W + (size_t)(n0 + r) * K + c4;
    for (int k0 = 0; k0 < K; k0 += 16) {
        float4 av = *(const float4*)(Aptr + k0);
        float4 wv = *(const float4*)(Wptr + k0);
        As[c4 + 0][r] = av.x; As[c4 + 1][r] = av.y; As[c4 + 2][r] = av.z; As[c4 + 3][r] = av.w;
        Ws[c4 + 0][r] = wv.x; Ws[c4 + 1][r] = wv.y; Ws[c4 + 2][r] = wv.z; Ws[c4 + 3][r] = wv.w;
        __syncthreads();
        #pragma unroll
        for (int kk = 0; kk < 16; kk++) {
            float4 a4 = *(const float4*)&As[kk][ty << 2];
            float4 b4 = *(const float4*)&Ws[kk][tx << 2];
            float a[4] = {a4.x, a4.y, a4.z, a4.w};
            float bb[4] = {b4.x, b4.y, b4.z, b4.w};
            #pragma unroll
            for (int i = 0; i < 4; i++)
                #pragma unroll
                for (int j = 0; j < 4; j++)
                    acc[i][j] = fmaf(a[i], bb[j], acc[i][j]);
        }
        __syncthreads();
    }
    int nn = n0 + (tx << 2);
    float4 bb = *(const float4*)&bias[nn];
    #pragma unroll
    for (int i = 0; i < 4; i++) {
        int m = m0 + (ty << 2) + i;
        float4 o;
        o.x = (acc[i][0] + bb.x) * scale;
        o.y = (acc[i][1] + bb.y) * scale;
        o.z = (acc[i][2] + bb.z) * scale;
        o.w = (acc[i][3] + bb.w) * scale;
        if (relu) {
            o.x = fmaxf(o.x, 0.f); o.y = fmaxf(o.y, 0.f);
            o.z = fmaxf(o.z, 0.f); o.w = fmaxf(o.w, 0.f);
        }
        if (resid) {
            float4 rr = *(const float4*)&resid[(size_t)m * N + nn];
            o.x += rr.x; o.y += rr.y; o.z += rr.z; o.w += rr.w;
        }
        *(float4*)&C[(size_t)m * N + nn] = o;
    }
}

// ---------------- S[b,h,q,bucket] = (q+v)[b,h,q,:] . rel[bucket, h, :] -----
__global__ __launch_bounds__(64) void srel_kernel(const float* __restrict__ vvec,
                                                  const float* __restrict__ rel) {
    __shared__ float qv[64];
    int idx = blockIdx.x;
    int q = idx & (T - 1);
    int h = (idx >> 8) & (H - 1);
    int b = idx >> 11;
    int tid = threadIdx.x;
    qv[tid] = g_q[((b * T) + q) * D + h * 64 + tid] + vvec[h * 64 + tid];
    __syncthreads();
    for (int bk = tid; bk < NBUCK; bk += 64) {
        const float* rr = rel + bk * D + h * 64;
        float acc = 0.f;
        #pragma unroll 16
        for (int d2 = 0; d2 < 64; d2++) acc += qv[d2] * rr[d2];
        g_srel[(((b * H) + h) * T + q) * NBUCK + bk] = acc;
    }
}

// ---------------- fused attention per (b,h): scores + rel-lookup + softmax + ctx
#define ATTN_SMEM_FLOATS (2*256*65 + 64 + 64 + 256 + 256 + 32)
__global__ __launch_bounds__(256) void attn_kernel(const int* __restrict__ distances,
                                                   const int* __restrict__ lengths,
                                                   const float* __restrict__ uvec) {
    extern __shared__ float sm[];
    float* Kt    = sm;                // 256 x 65 (padded, conflict-free)
    float* Vt    = Kt + 256 * 65;
    float* qu    = Vt + 256 * 65;     // 64
    float* srow  = qu + 64;           // 33 (padded to 64)
    float* probs = srow + 64;         // 256
    float* red   = probs + 256;       // 256
    float* sc    = red + 256;         // 32

    int bh = blockIdx.x;
    int b = bh >> 3, h = bh & 7;
    int q0 = blockIdx.y * (T / 2);
    int tid = threadIdx.x;
    int len = lengths[b];

    for (int idx = tid; idx < T * DH; idx += 256) {
        int t = idx >> 6, dh = idx & 63;
        Kt[t * 65 + dh] = g_k[((b * T) + t) * D + h * 64 + dh];
        Vt[t * 65 + dh] = g_v[((b * T) + t) * D + h * 64 + dh];
    }
    __syncthreads();

    for (int q = q0; q < q0 + T / 2; q++) {
        if (tid < 64)   qu[tid]   = g_q[((b * T) + q) * D + h * 64 + tid] + uvec[h * 64 + tid];
        if (tid < NBUCK) srow[tid] = g_srel[(((b * H) + h) * T + q) * NBUCK + tid];
        __syncthreads();

        float s;
        {
            const float* kr = Kt + tid * 65;
            float acc = 0.f;
            #pragma unroll
            for (int d2 = 0; d2 < 64; d2++) acc += qu[d2] * kr[d2];
            int bucket = distances[((b * T) + q) * T + tid];
            s = acc + srow[bucket];
            if (tid >= len) s = -1e30f;
        }
        float mx = blkMax(s, sc);
        float e = __expf(s - mx);
        probs[tid] = e;
        float ssum = blkSum(e, sc);      // entry-sync makes probs visible
        float inv = 1.0f / ssum;

        int dh = tid & 63, part = tid >> 6;
        const float* vbase = Vt + (part * 64) * 65 + dh;
        const float* pbase = probs + part * 64;
        float acc = 0.f;
        #pragma unroll 8
        for (int kk = 0; kk < 64; kk++) acc += pbase[kk] * vbase[kk * 65];
        red[part * 64 + dh] = acc;
        __syncthreads();
        if (tid < 64) {
            float c = (red[tid] + red[64 + tid] + red[128 + tid] + red[192 + tid]) * inv;
            g_ctx[((b * T) + q) * D + h * 64 + tid] = c;
        }
        __syncthreads();
    }
}

// ---------------- final LN + transpose (B,T,D) -> (T,B,D) ------------------
__global__ __launch_bounds__(128) void final_kernel(const float* __restrict__ gam,
                                                    const float* __restrict__ bet,
                                                    float* __restrict__ out) {
    __shared__ float sc[32];
    int tok = blockIdx.x;
    int b = tok / T, t = tok % T;
    int tid = threadIdx.x;
    const float4 vv = ((const float4*)(g_x + tok * D))[tid];
    float s = vv.x + vv.y + vv.z + vv.w;
    float mean = blkSum(s, sc) * (1.0f / D);
    float dx = vv.x - mean, dy = vv.y - mean, dz = vv.z - mean, dw = vv.w - mean;
    float sq = dx * dx + dy * dy + dz * dz + dw * dw;
    float var = blkSum(sq, sc) * (1.0f / D);
    float inv = rsqrtf(var + 1e-6f);
    float4 gv = ((const float4*)gam)[tid];
    float4 bv = ((const float4*)bet)[tid];
    float4 o;
    o.x = dx * inv * gv.x + bv.x;
    o.y = dy * inv * gv.y + bv.y;
    o.z = dz * inv * gv.z + bv.z;
    o.w = dw * inv * gv.w + bv.w;
    ((float4*)(out + ((t * B) + b) * D))[tid] = o;
}

// ---------------- host ----------------
extern "C" void kernel_launch(void* const* d_in, const int* in_sizes, int n_in,
                              void* d_out, int out_size) {
    // Input order per setup_inputs() dict insertion:
    // 0:src 1:lengths 2:distances 3:u 4:v 5:ln1_g 6:ln1_b
    // 7:Wq 8:Wk 9:Wv 10:Wo  (weights first!)
    // 11:bq 12:bk 13:bv 14:bo
    // 15:rel_table 16:ffn_ln_g 17:ffn_ln_b 18:W1 19:b1 20:W2 21:b2
    // 22:final_ln_g 23:final_ln_b
    const float* src       = (const float*)d_in[0];
    const int*   lengths   = (const int*)  d_in[1];
    const int*   distances = (const int*)  d_in[2];
    const float* u         = (const float*)d_in[3];
    const float* v         = (const float*)d_in[4];
    const float* ln1_g     = (const float*)d_in[5];
    const float* ln1_b     = (const float*)d_in[6];
    const float* Wq        = (const float*)d_in[7];
    const float* Wk        = (const float*)d_in[8];
    const float* Wv        = (const float*)d_in[9];
    const float* Wo        = (const float*)d_in[10];
    const float* bq        = (const float*)d_in[11];
    const float* bk        = (const float*)d_in[12];
    const float* bv        = (const float*)d_in[13];
    const float* bo        = (const float*)d_in[14];
    const float* rel_table = (const float*)d_in[15];
    const float* ffn_ln_g  = (const float*)d_in[16];
    const float* ffn_ln_b  = (const float*)d_in[17];
    const float* W1        = (const float*)d_in[18];
    const float* b1        = (const float*)d_in[19];
    const float* W2        = (const float*)d_in[20];
    const float* b2        = (const float*)d_in[21];
    const float* fin_g     = (const float*)d_in[22];
    const float* fin_b     = (const float*)d_in[23];
    float* out = (float*)d_out;

    float *px, *ph, *pq, *pk, *pv, *pctx, *pout, *phid;
    cudaGetSymbolAddress((void**)&px,   g_x);
    cudaGetSymbolAddress((void**)&ph,   g_h);
    cudaGetSymbolAddress((void**)&pq,   g_q);
    cudaGetSymbolAddress((void**)&pk,   g_k);
    cudaGetSymbolAddress((void**)&pv,   g_v);
    cudaGetSymbolAddress((void**)&pctx, g_ctx);
    cudaGetSymbolAddress((void**)&pout, g_out);
    cudaGetSymbolAddress((void**)&phid, g_hid);

    size_t attn_smem = ATTN_SMEM_FLOATS * sizeof(float);
    cudaFuncSetAttribute(attn_kernel, cudaFuncAttributeMaxDynamicSharedMemorySize, (int)attn_smem);

    embed_kernel<<<(MTOK * D + 255) / 256, 256>>>(src);

    const float qscale = 1.0f / sqrtf((float)DH);
    for (int l = 0; l < NL; l++) {
        ln_kernel<<<MTOK, 128>>>(px, ph, ln1_g + l * D, ln1_b + l * D);

        gemm_kernel<<<dim3(D / 64, MTOK / 64), 256>>>(ph, Wq + (size_t)l * D * D, bq + l * D, nullptr, pq, MTOK, D, D, qscale, 0);
        gemm_kernel<<<dim3(D / 64, MTOK / 64), 256>>>(ph, Wk + (size_t)l * D * D, bk + l * D, nullptr, pk, MTOK, D, D, 1.0f, 0);
        gemm_kernel<<<dim3(D / 64, MTOK / 64), 256>>>(ph, Wv + (size_t)l * D * D, bv + l * D, nullptr, pv, MTOK, D, D, 1.0f, 0);

        srel_kernel<<<B * H * T, 64>>>(v, rel_table + (size_t)l * NBUCK * D);

        attn_kernel<<<dim3(B * H, 2), 256, attn_smem>>>(distances, lengths, u);

        gemm_kernel<<<dim3(D / 64, MTOK / 64), 256>>>(pctx, Wo + (size_t)l * D * D, bo + l * D, px, pout, MTOK, D, D, 1.0f, 0);

        ln_kernel<<<MTOK, 128>>>(pout, ph, ffn_ln_g + l * D, ffn_ln_b + l * D);

        gemm_kernel<<<dim3(DFF / 64, MTOK / 64), 256>>>(ph, W1 + (size_t)l * DFF * D, b1 + l * DFF, nullptr, phid, MTOK, DFF, D, 1.0f, 1);
        gemm_kernel<<<dim3(D / 64, MTOK / 64), 256>>>(phid, W2 + (size_t)l * D * DFF, b2 + l * D, pout, px, MTOK, D, DFF, 1.0f, 0);
    }

    final_kernel<<<MTOK, 128>>>(fin_g, fin_b, out);
}

// round 3
// speedup vs baseline: 1.2068x; 1.2068x over previous
#include <cuda_runtime.h>
#include <cuda_bf16.h>
#include <math.h>

#define NL 4
#define D 512
#define H 8
#define DFF 2048
#define T 256
#define B 8
#define NBUCK 33
#define DH 64
#define MTOK (B*T)   // 2048

// weight bf16 buffer offsets (elements)
#define WQ_OFF 0
#define WK_OFF (4*D*D)
#define WV_OFF (2*4*D*D)
#define WO_OFF (3*4*D*D)
#define W1_OFF (4*4*D*D)
#define W2_OFF (4*4*D*D + 4*DFF*D)
#define WTOT   (4*4*D*D + 2*4*DFF*D)

// ---------------- scratch (device globals; no allocation allowed) ----------
__device__ float g_x[MTOK*D];
__device__ float g_q[MTOK*D];
__device__ float g_k[MTOK*D];
__device__ float g_v[MTOK*D];
__device__ float g_out[MTOK*D];
__device__ float g_srel[B*H*T*NBUCK];
__device__ __nv_bfloat16 g_hb[MTOK*D];        // LN outputs (GEMM A)
__device__ __nv_bfloat16 g_ctxb[MTOK*D];      // attention output (GEMM A)
__device__ __nv_bfloat16 g_hidb[MTOK*DFF];    // FFN hidden (GEMM A)
__device__ __nv_bfloat16 g_wbf[WTOT];         // all weights bf16

// ---------------- reductions ----------------
__device__ __forceinline__ float blkSum(float v, float* sc) {
    __syncthreads();
    int tid = threadIdx.x, lane = tid & 31, w = tid >> 5, nw = blockDim.x >> 5;
    #pragma unroll
    for (int o = 16; o; o >>= 1) v += __shfl_xor_sync(0xffffffffu, v, o);
    if (lane == 0) sc[w] = v;
    __syncthreads();
    if (tid == 0) { float t = 0.f; for (int i = 0; i < nw; i++) t += sc[i]; sc[0] = t; }
    __syncthreads();
    return sc[0];
}
__device__ __forceinline__ float blkMax(float v, float* sc) {
    __syncthreads();
    int tid = threadIdx.x, lane = tid & 31, w = tid >> 5, nw = blockDim.x >> 5;
    #pragma unroll
    for (int o = 16; o; o >>= 1) v = fmaxf(v, __shfl_xor_sync(0xffffffffu, v, o));
    if (lane == 0) sc[w] = v;
    __syncthreads();
    if (tid == 0) { float t = -3.0e38f; for (int i = 0; i < nw; i++) t = fmaxf(t, sc[i]); sc[0] = t; }
    __syncthreads();
    return sc[0];
}

// ---------------- weight conversion fp32 -> bf16 ---------------------------
__global__ void f2bf4_kernel(const float* __restrict__ in, __nv_bfloat16* __restrict__ out, int n4) {
    int i = blockIdx.x * blockDim.x + threadIdx.x;
    if (i >= n4) return;
    float4 v = ((const float4*)in)[i];
    __nv_bfloat162* o = (__nv_bfloat162*)out;
    o[2*i]   = __floats2bfloat162_rn(v.x, v.y);
    o[2*i+1] = __floats2bfloat162_rn(v.z, v.w);
}

// ---------------- embedding ------------------------------------------------
__global__ void embed_kernel(const float* __restrict__ src) {
    int i = blockIdx.x * blockDim.x + threadIdx.x;
    if (i >= MTOK * D) return;
    int d = i & (D - 1);
    int t = (i / D) & (T - 1);
    int b = i / (D * T);
    float ang = (float)t * expf(-(float)(d & ~1) * (logf(10000.0f) / (float)D));
    float pe = (d & 1) ? cosf(ang) : sinf(ang);
    g_x[i] = src[((t * B) + b) * D + d] * sqrtf((float)D) + pe;
}

// ---------------- layernorm -> bf16 output ---------------------------------
__global__ __launch_bounds__(128) void ln_kernel(const float* __restrict__ in,
                                                 __nv_bfloat16* __restrict__ out,
                                                 const float* __restrict__ gam,
                                                 const float* __restrict__ bet) {
    __shared__ float sc[32];
    int tok = blockIdx.x;
    int tid = threadIdx.x;
    const float4 vv = ((const float4*)(in + tok * D))[tid];
    float s = vv.x + vv.y + vv.z + vv.w;
    float mean = blkSum(s, sc) * (1.0f / D);
    float dx = vv.x - mean, dy = vv.y - mean, dz = vv.z - mean, dw = vv.w - mean;
    float sq = dx * dx + dy * dy + dz * dz + dw * dw;
    float var = blkSum(sq, sc) * (1.0f / D);
    float inv = rsqrtf(var + 1e-6f);
    float4 gv = ((const float4*)gam)[tid];
    float4 bv = ((const float4*)bet)[tid];
    __nv_bfloat162* o2 = (__nv_bfloat162*)(out + tok * D);
    o2[2*tid]   = __floats2bfloat162_rn(dx * inv * gv.x + bv.x, dy * inv * gv.y + bv.y);
    o2[2*tid+1] = __floats2bfloat162_rn(dz * inv * gv.z + bv.z, dw * inv * gv.w + bv.w);
}

// ---------------- tensor-core GEMM -----------------------------------------
// C[M,N] = scale*(A[M,K](bf16) @ W[N,K](bf16)^T + bias) (+relu)(+resid fp32)
// outputs: Cf (fp32) and/or Cb (bf16)
// block tile 128(M) x 64(N), BK=64; 8 warps as 4(m) x 2(n), warp tile 32x32
#define GP 72   // padded smem row stride (bf16 elems)
__device__ __forceinline__ void mma_bf16(float* d, const unsigned* a, unsigned b0, unsigned b1) {
    asm volatile("mma.sync.aligned.m16n8k16.row.col.f32.bf16.bf16.f32 "
        "{%0,%1,%2,%3},{%4,%5,%6,%7},{%8,%9},{%0,%1,%2,%3};\n"
        : "+f"(d[0]), "+f"(d[1]), "+f"(d[2]), "+f"(d[3])
        : "r"(a[0]), "r"(a[1]), "r"(a[2]), "r"(a[3]), "r"(b0), "r"(b1));
}
__device__ __forceinline__ void ldsm4(unsigned* r, unsigned addr) {
    asm volatile("ldmatrix.sync.aligned.m8n8.x4.shared.b16 {%0,%1,%2,%3},[%4];\n"
        : "=r"(r[0]), "=r"(r[1]), "=r"(r[2]), "=r"(r[3]) : "r"(addr));
}

__global__ __launch_bounds__(256) void gemm_tc_kernel(
    const __nv_bfloat16* __restrict__ A, const __nv_bfloat16* __restrict__ W,
    const float* __restrict__ bias, const float* __restrict__ resid,
    float* __restrict__ Cf, __nv_bfloat16* __restrict__ Cb,
    int M, int N, int K, float scale, int relu)
{
    __shared__ __nv_bfloat16 As[128 * GP];
    __shared__ __nv_bfloat16 Bs[64 * GP];
    int tid = threadIdx.x;
    int lane = tid & 31, wid = tid >> 5;
    int wm = wid & 3, wn = wid >> 2;
    int m0 = blockIdx.y << 7, n0 = blockIdx.x << 6;

    // ldmatrix per-lane offsets
    int a_row = (wm << 5) + (lane & 15);
    int a_koff = (lane >> 4) << 3;
    int b_row = (wn << 5) + (lane & 7) + ((lane >> 4) << 3);
    int b_koff = ((lane >> 3) & 1) << 3;
    unsigned As_base = (unsigned)__cvta_generic_to_shared(As);
    unsigned Bs_base = (unsigned)__cvta_generic_to_shared(Bs);

    float acc[2][4][4];
    #pragma unroll
    for (int i = 0; i < 2; i++)
        #pragma unroll
        for (int j = 0; j < 4; j++)
            #pragma unroll
            for (int r = 0; r < 4; r++) acc[i][j][r] = 0.f;

    const int KT = K >> 6;
    uint4 ar[4], br[2];
    // chunk coords (uint4 = 8 bf16)
    int ca_row[4], ca_kc[4], cb_row[2], cb_kc[2];
    #pragma unroll
    for (int i = 0; i < 4; i++) { int c = tid + (i << 8); ca_row[i] = c >> 3; ca_kc[i] = (c & 7) << 3; }
    #pragma unroll
    for (int i = 0; i < 2; i++) { int c = tid + (i << 8); cb_row[i] = c >> 3; cb_kc[i] = (c & 7) << 3; }

    const __nv_bfloat16* Ag = A + (size_t)m0 * K;
    const __nv_bfloat16* Wg = W + (size_t)n0 * K;

    // prefetch tile 0
    #pragma unroll
    for (int i = 0; i < 4; i++) ar[i] = *(const uint4*)(Ag + (size_t)ca_row[i] * K + ca_kc[i]);
    #pragma unroll
    for (int i = 0; i < 2; i++) br[i] = *(const uint4*)(Wg + (size_t)cb_row[i] * K + cb_kc[i]);
    #pragma unroll
    for (int i = 0; i < 4; i++) *(uint4*)&As[ca_row[i] * GP + ca_kc[i]] = ar[i];
    #pragma unroll
    for (int i = 0; i < 2; i++) *(uint4*)&Bs[cb_row[i] * GP + cb_kc[i]] = br[i];
    __syncthreads();

    for (int kt = 1; kt <= KT; kt++) {
        if (kt < KT) {
            const __nv_bfloat16* Agk = Ag + (kt << 6);
            const __nv_bfloat16* Wgk = Wg + (kt << 6);
            #pragma unroll
            for (int i = 0; i < 4; i++) ar[i] = *(const uint4*)(Agk + (size_t)ca_row[i] * K + ca_kc[i]);
            #pragma unroll
            for (int i = 0; i < 2; i++) br[i] = *(const uint4*)(Wgk + (size_t)cb_row[i] * K + cb_kc[i]);
        }
        // compute on current smem tile: 4 k-steps of 16
        #pragma unroll
        for (int s = 0; s < 4; s++) {
            unsigned av[2][4], bv[2][4];
            unsigned abase = As_base + (unsigned)((a_row * GP + (s << 4) + a_koff) << 1);
            unsigned bbase = Bs_base + (unsigned)((b_row * GP + (s << 4) + b_koff) << 1);
            ldsm4(av[0], abase);
            ldsm4(av[1], abase + (16 * GP * 2));
            ldsm4(bv[0], bbase);
            ldsm4(bv[1], bbase + (16 * GP * 2));
            #pragma unroll
            for (int i = 0; i < 2; i++)
                #pragma unroll
                for (int j = 0; j < 2; j++) {
                    mma_bf16(acc[i][2*j],   av[i], bv[j][0], bv[j][1]);
                    mma_bf16(acc[i][2*j+1], av[i], bv[j][2], bv[j][3]);
                }
        }
        if (kt < KT) {
            __syncthreads();
            #pragma unroll
            for (int i = 0; i < 4; i++) *(uint4*)&As[ca_row[i] * GP + ca_kc[i]] = ar[i];
            #pragma unroll
            for (int i = 0; i < 2; i++) *(uint4*)&Bs[cb_row[i] * GP + cb_kc[i]] = br[i];
            __syncthreads();
        }
    }

    // epilogue
    int rbase = m0 + (wm << 5) + (lane >> 2);
    int cbase = n0 + (wn << 5) + ((lane & 3) << 1);
    #pragma unroll
    for (int i = 0; i < 2; i++) {
        #pragma unroll
        for (int j = 0; j < 4; j++) {
            int r0 = rbase + (i << 4);
            int cc = cbase + (j << 3);
            float2 bb = *(const float2*)&bias[cc];
            float o0 = (acc[i][j][0] + bb.x) * scale;
            float o1 = (acc[i][j][1] + bb.y) * scale;
            float o2 = (acc[i][j][2] + bb.x) * scale;
            float o3 = (acc[i][j][3] + bb.y) * scale;
            if (relu) {
                o0 = fmaxf(o0, 0.f); o1 = fmaxf(o1, 0.f);
                o2 = fmaxf(o2, 0.f); o3 = fmaxf(o3, 0.f);
            }
            if (resid) {
                float2 ra = *(const float2*)&resid[(size_t)r0 * N + cc];
                float2 rb = *(const float2*)&resid[(size_t)(r0 + 8) * N + cc];
                o0 += ra.x; o1 += ra.y; o2 += rb.x; o3 += rb.y;
            }
            if (Cf) {
                *(float2*)&Cf[(size_t)r0 * N + cc] = make_float2(o0, o1);
                *(float2*)&Cf[(size_t)(r0 + 8) * N + cc] = make_float2(o2, o3);
            }
            if (Cb) {
                *(__nv_bfloat162*)&Cb[(size_t)r0 * N + cc] = __floats2bfloat162_rn(o0, o1);
                *(__nv_bfloat162*)&Cb[(size_t)(r0 + 8) * N + cc] = __floats2bfloat162_rn(o2, o3);
            }
        }
    }
}

// ---------------- S[b,h,q,bucket] = (q+v)[b,h,q,:] . rel[bucket, h, :] -----
__global__ __launch_bounds__(64) void srel_kernel(const float* __restrict__ vvec,
                                                  const float* __restrict__ rel) {
    __shared__ float qv[64];
    int idx = blockIdx.x;
    int q = idx & (T - 1);
    int h = (idx >> 8) & (H - 1);
    int b = idx >> 11;
    int tid = threadIdx.x;
    qv[tid] = g_q[((b * T) + q) * D + h * 64 + tid] + vvec[h * 64 + tid];
    __syncthreads();
    for (int bk = tid; bk < NBUCK; bk += 64) {
        const float* rr = rel + bk * D + h * 64;
        float acc = 0.f;
        #pragma unroll 16
        for (int d2 = 0; d2 < 64; d2++) acc += qv[d2] * rr[d2];
        g_srel[(((b * H) + h) * T + q) * NBUCK + bk] = acc;
    }
}

// ---------------- fused attention per (b,h) --------------------------------
#define ATTN_SMEM_FLOATS (2*256*65 + 64 + 64 + 256 + 256 + 32)
__global__ __launch_bounds__(256) void attn_kernel(const int* __restrict__ distances,
                                                   const int* __restrict__ lengths,
                                                   const float* __restrict__ uvec) {
    extern __shared__ float sm[];
    float* Kt    = sm;
    float* Vt    = Kt + 256 * 65;
    float* qu    = Vt + 256 * 65;
    float* srow  = qu + 64;
    float* probs = srow + 64;
    float* red   = probs + 256;
    float* sc    = red + 256;

    int bh = blockIdx.x;
    int b = bh >> 3, h = bh & 7;
    int q0 = blockIdx.y * (T / 2);
    int tid = threadIdx.x;
    int len = lengths[b];

    for (int idx = tid; idx < T * DH; idx += 256) {
        int t = idx >> 6, dh = idx & 63;
        Kt[t * 65 + dh] = g_k[((b * T) + t) * D + h * 64 + dh];
        Vt[t * 65 + dh] = g_v[((b * T) + t) * D + h * 64 + dh];
    }
    __syncthreads();

    for (int q = q0; q < q0 + T / 2; q++) {
        if (tid < 64)    qu[tid]   = g_q[((b * T) + q) * D + h * 64 + tid] + uvec[h * 64 + tid];
        if (tid < NBUCK) srow[tid] = g_srel[(((b * H) + h) * T + q) * NBUCK + tid];
        __syncthreads();

        float s;
        {
            const float* kr = Kt + tid * 65;
            float acc = 0.f;
            #pragma unroll
            for (int d2 = 0; d2 < 64; d2++) acc += qu[d2] * kr[d2];
            int bucket = distances[((b * T) + q) * T + tid];
            s = acc + srow[bucket];
            if (tid >= len) s = -1e30f;
        }
        float mx = blkMax(s, sc);
        float e = __expf(s - mx);
        probs[tid] = e;
        float ssum = blkSum(e, sc);
        float inv = 1.0f / ssum;

        int dh = tid & 63, part = tid >> 6;
        const float* vbase = Vt + (part * 64) * 65 + dh;
        const float* pbase = probs + part * 64;
        float acc = 0.f;
        #pragma unroll 8
        for (int kk = 0; kk < 64; kk++) acc += pbase[kk] * vbase[kk * 65];
        red[part * 64 + dh] = acc;
        __syncthreads();
        if (tid < 64) {
            float c = (red[tid] + red[64 + tid] + red[128 + tid] + red[192 + tid]) * inv;
            g_ctxb[((b * T) + q) * D + h * 64 + tid] = __float2bfloat16(c);
        }
        __syncthreads();
    }
}

// ---------------- final LN + transpose (B,T,D) -> (T,B,D) ------------------
__global__ __launch_bounds__(128) void final_kernel(const float* __restrict__ gam,
                                                    const float* __restrict__ bet,
                                                    float* __restrict__ out) {
    __shared__ float sc[32];
    int tok = blockIdx.x;
    int b = tok / T, t = tok % T;
    int tid = threadIdx.x;
    const float4 vv = ((const float4*)(g_x + tok * D))[tid];
    float s = vv.x + vv.y + vv.z + vv.w;
    float mean = blkSum(s, sc) * (1.0f / D);
    float dx = vv.x - mean, dy = vv.y - mean, dz = vv.z - mean, dw = vv.w - mean;
    float sq = dx * dx + dy * dy + dz * dz + dw * dw;
    float var = blkSum(sq, sc) * (1.0f / D);
    float inv = rsqrtf(var + 1e-6f);
    float4 gv = ((const float4*)gam)[tid];
    float4 bv = ((const float4*)bet)[tid];
    float4 o;
    o.x = dx * inv * gv.x + bv.x;
    o.y = dy * inv * gv.y + bv.y;
    o.z = dz * inv * gv.z + bv.z;
    o.w = dw * inv * gv.w + bv.w;
    ((float4*)(out + ((t * B) + b) * D))[tid] = o;
}

// ---------------- host ----------------
extern "C" void kernel_launch(void* const* d_in, const int* in_sizes, int n_in,
                              void* d_out, int out_size) {
    const float* src       = (const float*)d_in[0];
    const int*   lengths   = (const int*)  d_in[1];
    const int*   distances = (const int*)  d_in[2];
    const float* u         = (const float*)d_in[3];
    const float* v         = (const float*)d_in[4];
    const float* ln1_g     = (const float*)d_in[5];
    const float* ln1_b     = (const float*)d_in[6];
    const float* Wq        = (const float*)d_in[7];
    const float* Wk        = (const float*)d_in[8];
    const float* Wv        = (const float*)d_in[9];
    const float* Wo        = (const float*)d_in[10];
    const float* bq        = (const float*)d_in[11];
    const float* bk        = (const float*)d_in[12];
    const float* bv        = (const float*)d_in[13];
    const float* bo        = (const float*)d_in[14];
    const float* rel_table = (const float*)d_in[15];
    const float* ffn_ln_g  = (const float*)d_in[16];
    const float* ffn_ln_b  = (const float*)d_in[17];
    const float* W1        = (const float*)d_in[18];
    const float* b1        = (const float*)d_in[19];
    const float* W2        = (const float*)d_in[20];
    const float* b2        = (const float*)d_in[21];
    const float* fin_g     = (const float*)d_in[22];
    const float* fin_b     = (const float*)d_in[23];
    float* out = (float*)d_out;

    float *px, *pq, *pk, *pv, *pout;
    __nv_bfloat16 *phb, *pctxb, *phidb, *pwbf;
    cudaGetSymbolAddress((void**)&px,    g_x);
    cudaGetSymbolAddress((void**)&pq,    g_q);
    cudaGetSymbolAddress((void**)&pk,    g_k);
    cudaGetSymbolAddress((void**)&pv,    g_v);
    cudaGetSymbolAddress((void**)&pout,  g_out);
    cudaGetSymbolAddress((void**)&phb,   g_hb);
    cudaGetSymbolAddress((void**)&pctxb, g_ctxb);
    cudaGetSymbolAddress((void**)&phidb, g_hidb);
    cudaGetSymbolAddress((void**)&pwbf,  g_wbf);

    size_t attn_smem = ATTN_SMEM_FLOATS * sizeof(float);
    cudaFuncSetAttribute(attn_kernel, cudaFuncAttributeMaxDynamicSharedMemorySize, (int)attn_smem);

    // convert weights to bf16
    {
        int nqk = 4 * D * D;          // per projection family (all layers)
        int nff = 4 * DFF * D;
        f2bf4_kernel<<<(nqk/4 + 255)/256, 256>>>(Wq, pwbf + WQ_OFF, nqk/4);
        f2bf4_kernel<<<(nqk/4 + 255)/256, 256>>>(Wk, pwbf + WK_OFF, nqk/4);
        f2bf4_kernel<<<(nqk/4 + 255)/256, 256>>>(Wv, pwbf + WV_OFF, nqk/4);
        f2bf4_kernel<<<(nqk/4 + 255)/256, 256>>>(Wo, pwbf + WO_OFF, nqk/4);
        f2bf4_kernel<<<(nff/4 + 255)/256, 256>>>(W1, pwbf + W1_OFF, nff/4);
        f2bf4_kernel<<<(nff/4 + 255)/256, 256>>>(W2, pwbf + W2_OFF, nff/4);
    }

    embed_kernel<<<(MTOK * D + 255) / 256, 256>>>(src);

    const float qscale = 1.0f / sqrtf((float)DH);
    for (int l = 0; l < NL; l++) {
        ln_kernel<<<MTOK, 128>>>(px, phb, ln1_g + l * D, ln1_b + l * D);

        gemm_tc_kernel<<<dim3(D/64, MTOK/128), 256>>>(phb, pwbf + WQ_OFF + (size_t)l*D*D, bq + l*D, nullptr, pq, nullptr, MTOK, D, D, qscale, 0);
        gemm_tc_kernel<<<dim3(D/64, MTOK/128), 256>>>(phb, pwbf + WK_OFF + (size_t)l*D*D, bk + l*D, nullptr, pk, nullptr, MTOK, D, D, 1.0f, 0);
        gemm_tc_kernel<<<dim3(D/64, MTOK/128), 256>>>(phb, pwbf + WV_OFF + (size_t)l*D*D, bv + l*D, nullptr, pv, nullptr, MTOK, D, D, 1.0f, 0);

        srel_kernel<<<B * H * T, 64>>>(v, rel_table + (size_t)l * NBUCK * D);

        attn_kernel<<<dim3(B * H, 2), 256, attn_smem>>>(distances, lengths, u);

        gemm_tc_kernel<<<dim3(D/64, MTOK/128), 256>>>(pctxb, pwbf + WO_OFF + (size_t)l*D*D, bo + l*D, px, pout, nullptr, MTOK, D, D, 1.0f, 0);

        ln_kernel<<<MTOK, 128>>>(pout, phb, ffn_ln_g + l * D, ffn_ln_b + l * D);

        gemm_tc_kernel<<<dim3(DFF/64, MTOK/128), 256>>>(phb, pwbf + W1_OFF + (size_t)l*DFF*D, b1 + l*DFF, nullptr, nullptr, phidb, MTOK, DFF, D, 1.0f, 1);
        gemm_tc_kernel<<<dim3(D/64, MTOK/128), 256>>>(phidb, pwbf + W2_OFF + (size_t)l*DFF*D, b2 + l*D, pout, px, nullptr, MTOK, D, DFF, 1.0f, 0);
    }

    final_kernel<<<MTOK, 128>>>(fin_g, fin_b, out);
}

// round 4
// speedup vs baseline: 2.7814x; 2.3047x over previous
#include <cuda_runtime.h>
#include <cuda_bf16.h>
#include <math.h>

#define NL 4
#define D 512
#define H 8
#define DFF 2048
#define T 256
#define B 8
#define NBUCK 33
#define DH 64
#define MTOK (B*T)   // 2048
#define NQKV 1536

// bf16 weight buffer offsets (elements)
#define QKVW_OFF 0
#define WO_OFF   (NL*NQKV*D)                    // 3145728
#define W1_OFF   (WO_OFF + NL*D*D)              // 4194304
#define W2_OFF   (W1_OFF + NL*DFF*D)            // 8388608
#define WTOT     (W2_OFF + NL*D*DFF)            // 12582912

// ---------------- scratch (device globals; no allocation allowed) ----------
__device__ float g_x[MTOK*D];
__device__ float g_out[MTOK*D];
__device__ float g_qkv[MTOK*NQKV];
__device__ float g_srel[B*H*T*NBUCK];
__device__ float g_bqkv[NL*NQKV];
__device__ __nv_bfloat16 g_hb[MTOK*D];
__device__ __nv_bfloat16 g_ctxb[MTOK*D];
__device__ __nv_bfloat16 g_hidb[MTOK*DFF];
__device__ __nv_bfloat16 g_wbf[WTOT];

// ---------------- reductions ----------------
__device__ __forceinline__ float blkSum(float v, float* sc) {
    __syncthreads();
    int tid = threadIdx.x, lane = tid & 31, w = tid >> 5, nw = blockDim.x >> 5;
    #pragma unroll
    for (int o = 16; o; o >>= 1) v += __shfl_xor_sync(0xffffffffu, v, o);
    if (lane == 0) sc[w] = v;
    __syncthreads();
    if (tid == 0) { float t = 0.f; for (int i = 0; i < nw; i++) t += sc[i]; sc[0] = t; }
    __syncthreads();
    return sc[0];
}

// ---------------- conversion kernels ---------------------------------------
__global__ void f2bf4_kernel(const float* __restrict__ in, __nv_bfloat16* __restrict__ out, int n4) {
    int i = blockIdx.x * blockDim.x + threadIdx.x;
    if (i >= n4) return;
    float4 v = ((const float4*)in)[i];
    __nv_bfloat162* o = (__nv_bfloat162*)out;
    o[2*i]   = __floats2bfloat162_rn(v.x, v.y);
    o[2*i+1] = __floats2bfloat162_rn(v.z, v.w);
}

// repack Wq/Wk/Wv into per-layer [1536,512] bf16
__global__ void qkvw_kernel(const float* __restrict__ Wq, const float* __restrict__ Wk,
                            const float* __restrict__ Wv, __nv_bfloat16* __restrict__ out) {
    int i = blockIdx.x * blockDim.x + threadIdx.x;   // float4 granule
    if (i >= NL*NQKV*D/4) return;
    int e = i * 4;
    int l = e / (NQKV*D);
    int rem = e - l * (NQKV*D);
    int r = rem / D;
    int c = rem - r * D;
    const float* src = (r < 512) ? Wq : (r < 1024) ? Wk : Wv;
    int rr = r & 511;
    float4 v = *(const float4*)(src + (size_t)l*D*D + (size_t)rr*D + c);
    __nv_bfloat162* o = (__nv_bfloat162*)(out + e);
    o[0] = __floats2bfloat162_rn(v.x, v.y);
    o[1] = __floats2bfloat162_rn(v.z, v.w);
}

__global__ void bqkv_kernel(const float* __restrict__ bq, const float* __restrict__ bk,
                            const float* __restrict__ bv, float* __restrict__ out) {
    int i = blockIdx.x * blockDim.x + threadIdx.x;
    if (i >= NL*NQKV) return;
    int l = i / NQKV, n = i - l*NQKV;
    float v = (n < 512) ? bq[l*D + n] : (n < 1024) ? bk[l*D + n - 512] : bv[l*D + n - 1024];
    out[i] = v;
}

// ---------------- embedding ------------------------------------------------
__global__ void embed_kernel(const float* __restrict__ src) {
    int i = blockIdx.x * blockDim.x + threadIdx.x;
    if (i >= MTOK * D) return;
    int d = i & (D - 1);
    int t = (i / D) & (T - 1);
    int b = i / (D * T);
    float ang = (float)t * expf(-(float)(d & ~1) * (logf(10000.0f) / (float)D));
    float pe = (d & 1) ? cosf(ang) : sinf(ang);
    g_x[i] = src[((t * B) + b) * D + d] * sqrtf((float)D) + pe;
}

// ---------------- layernorm -> bf16 ----------------------------------------
__global__ __launch_bounds__(128) void ln_kernel(const float* __restrict__ in,
                                                 __nv_bfloat16* __restrict__ out,
                                                 const float* __restrict__ gam,
                                                 const float* __restrict__ bet) {
    __shared__ float sc[32];
    int tok = blockIdx.x;
    int tid = threadIdx.x;
    const float4 vv = ((const float4*)(in + tok * D))[tid];
    float s = vv.x + vv.y + vv.z + vv.w;
    float mean = blkSum(s, sc) * (1.0f / D);
    float dx = vv.x - mean, dy = vv.y - mean, dz = vv.z - mean, dw = vv.w - mean;
    float sq = dx * dx + dy * dy + dz * dz + dw * dw;
    float var = blkSum(sq, sc) * (1.0f / D);
    float inv = rsqrtf(var + 1e-6f);
    float4 gv = ((const float4*)gam)[tid];
    float4 bv = ((const float4*)bet)[tid];
    __nv_bfloat162* o2 = (__nv_bfloat162*)(out + tok * D);
    o2[2*tid]   = __floats2bfloat162_rn(dx * inv * gv.x + bv.x, dy * inv * gv.y + bv.y);
    o2[2*tid+1] = __floats2bfloat162_rn(dz * inv * gv.z + bv.z, dw * inv * gv.w + bv.w);
}

// ---------------- tensor-core GEMM with cp.async 2-stage pipeline ----------
#define GP 72
__device__ __forceinline__ void mma_bf16(float* d, const unsigned* a, unsigned b0, unsigned b1) {
    asm volatile("mma.sync.aligned.m16n8k16.row.col.f32.bf16.bf16.f32 "
        "{%0,%1,%2,%3},{%4,%5,%6,%7},{%8,%9},{%0,%1,%2,%3};\n"
        : "+f"(d[0]), "+f"(d[1]), "+f"(d[2]), "+f"(d[3])
        : "r"(a[0]), "r"(a[1]), "r"(a[2]), "r"(a[3]), "r"(b0), "r"(b1));
}
__device__ __forceinline__ void ldsm4(unsigned* r, unsigned addr) {
    asm volatile("ldmatrix.sync.aligned.m8n8.x4.shared.b16 {%0,%1,%2,%3},[%4];\n"
        : "=r"(r[0]), "=r"(r[1]), "=r"(r[2]), "=r"(r[3]) : "r"(addr));
}
__device__ __forceinline__ void cp16(unsigned dst, const void* src) {
    asm volatile("cp.async.cg.shared.global [%0], [%1], 16;\n" :: "r"(dst), "l"(src));
}
__device__ __forceinline__ void cp_commit() { asm volatile("cp.async.commit_group;\n"); }
__device__ __forceinline__ void cp_wait0() { asm volatile("cp.async.wait_group 0;\n"); }

#define GEMM_SMEM ((2*128*GP + 2*64*GP) * 2)

__global__ __launch_bounds__(256) void gemm_tc_kernel(
    const __nv_bfloat16* __restrict__ A, const __nv_bfloat16* __restrict__ W,
    const float* __restrict__ bias, const float* __restrict__ resid,
    float* __restrict__ Cf, __nv_bfloat16* __restrict__ Cb,
    int M, int N, int K, float scale, int n_lo, int relu)
{
    extern __shared__ __nv_bfloat16 smg[];
    __nv_bfloat16* As = smg;               // [2][128*GP]
    __nv_bfloat16* Bs = smg + 2*128*GP;    // [2][64*GP]
    int tid = threadIdx.x;
    int lane = tid & 31, wid = tid >> 5;
    int wm = wid & 3, wn = wid >> 2;
    int m0 = blockIdx.y << 7, n0 = blockIdx.x << 6;

    int a_row = (wm << 5) + (lane & 15);
    int a_koff = (lane >> 4) << 3;
    int b_row = (wn << 5) + (lane & 7) + ((lane >> 4) << 3);
    int b_koff = ((lane >> 3) & 1) << 3;
    unsigned As_base = (unsigned)__cvta_generic_to_shared(As);
    unsigned Bs_base = (unsigned)__cvta_generic_to_shared(Bs);

    float acc[2][4][4];
    #pragma unroll
    for (int i = 0; i < 2; i++)
        #pragma unroll
        for (int j = 0; j < 4; j++)
            #pragma unroll
            for (int r = 0; r < 4; r++) acc[i][j][r] = 0.f;

    const int KT = K >> 6;
    int ca_row[4], ca_kc[4], cb_row[2], cb_kc[2];
    #pragma unroll
    for (int i = 0; i < 4; i++) { int c = tid + (i << 8); ca_row[i] = c >> 3; ca_kc[i] = (c & 7) << 3; }
    #pragma unroll
    for (int i = 0; i < 2; i++) { int c = tid + (i << 8); cb_row[i] = c >> 3; cb_kc[i] = (c & 7) << 3; }

    const __nv_bfloat16* Ag = A + (size_t)m0 * K;
    const __nv_bfloat16* Wg = W + (size_t)n0 * K;

    // issue stage load
    auto issue = [&](int kt, int s) {
        const __nv_bfloat16* a = Ag + (kt << 6);
        const __nv_bfloat16* w = Wg + (kt << 6);
        unsigned sa = As_base + (unsigned)((s * 128 * GP) << 1);
        unsigned sb = Bs_base + (unsigned)((s * 64 * GP) << 1);
        #pragma unroll
        for (int i = 0; i < 4; i++)
            cp16(sa + (unsigned)((ca_row[i] * GP + ca_kc[i]) << 1), a + (size_t)ca_row[i] * K + ca_kc[i]);
        #pragma unroll
        for (int i = 0; i < 2; i++)
            cp16(sb + (unsigned)((cb_row[i] * GP + cb_kc[i]) << 1), w + (size_t)cb_row[i] * K + cb_kc[i]);
        cp_commit();
    };

    issue(0, 0);
    for (int kt = 0; kt < KT; kt++) {
        int s = kt & 1;
        cp_wait0();
        __syncthreads();
        if (kt + 1 < KT) issue(kt + 1, s ^ 1);
        unsigned sa = As_base + (unsigned)((s * 128 * GP) << 1);
        unsigned sb = Bs_base + (unsigned)((s * 64 * GP) << 1);
        #pragma unroll
        for (int st = 0; st < 4; st++) {
            unsigned av[2][4], bv[2][4];
            unsigned abase = sa + (unsigned)((a_row * GP + (st << 4) + a_koff) << 1);
            unsigned bbase = sb + (unsigned)((b_row * GP + (st << 4) + b_koff) << 1);
            ldsm4(av[0], abase);
            ldsm4(av[1], abase + (16 * GP * 2));
            ldsm4(bv[0], bbase);
            ldsm4(bv[1], bbase + (16 * GP * 2));
            #pragma unroll
            for (int i = 0; i < 2; i++)
                #pragma unroll
                for (int j = 0; j < 2; j++) {
                    mma_bf16(acc[i][2*j],   av[i], bv[j][0], bv[j][1]);
                    mma_bf16(acc[i][2*j+1], av[i], bv[j][2], bv[j][3]);
                }
        }
        __syncthreads();
    }

    float sc = (n0 < n_lo) ? scale : 1.0f;
    int rbase = m0 + (wm << 5) + (lane >> 2);
    int cbase = n0 + (wn << 5) + ((lane & 3) << 1);
    #pragma unroll
    for (int i = 0; i < 2; i++) {
        #pragma unroll
        for (int j = 0; j < 4; j++) {
            int r0 = rbase + (i << 4);
            int cc = cbase + (j << 3);
            float2 bb = *(const float2*)&bias[cc];
            float o0 = (acc[i][j][0] + bb.x) * sc;
            float o1 = (acc[i][j][1] + bb.y) * sc;
            float o2 = (acc[i][j][2] + bb.x) * sc;
            float o3 = (acc[i][j][3] + bb.y) * sc;
            if (relu) {
                o0 = fmaxf(o0, 0.f); o1 = fmaxf(o1, 0.f);
                o2 = fmaxf(o2, 0.f); o3 = fmaxf(o3, 0.f);
            }
            if (resid) {
                float2 ra = *(const float2*)&resid[(size_t)r0 * N + cc];
                float2 rb = *(const float2*)&resid[(size_t)(r0 + 8) * N + cc];
                o0 += ra.x; o1 += ra.y; o2 += rb.x; o3 += rb.y;
            }
            if (Cf) {
                *(float2*)&Cf[(size_t)r0 * N + cc] = make_float2(o0, o1);
                *(float2*)&Cf[(size_t)(r0 + 8) * N + cc] = make_float2(o2, o3);
            }
            if (Cb) {
                *(__nv_bfloat162*)&Cb[(size_t)r0 * N + cc] = __floats2bfloat162_rn(o0, o1);
                *(__nv_bfloat162*)&Cb[(size_t)(r0 + 8) * N + cc] = __floats2bfloat162_rn(o2, o3);
            }
        }
    }
}

// ---------------- S[b,h,q,bucket] = (q+v)[b,h,q,:] . rel[bucket,h,:] -------
__global__ __launch_bounds__(64) void srel_kernel(const float* __restrict__ vvec,
                                                  const float* __restrict__ rel) {
    __shared__ float qv[64];
    int idx = blockIdx.x;
    int q = idx & (T - 1);
    int h = (idx >> 8) & (H - 1);
    int b = idx >> 11;
    int tid = threadIdx.x;
    qv[tid] = g_qkv[(size_t)((b * T) + q) * NQKV + h * 64 + tid] + vvec[h * 64 + tid];
    __syncthreads();
    for (int bk = tid; bk < NBUCK; bk += 64) {
        const float* rr = rel + bk * D + h * 64;
        float acc = 0.f;
        #pragma unroll 16
        for (int d2 = 0; d2 < 64; d2++) acc += qv[d2] * rr[d2];
        g_srel[(size_t)(((b * H) + h) * T + q) * NBUCK + bk] = acc;
    }
}

// ---------------- warp-parallel fused attention ----------------------------
// smem: f4K 16384 floats | fV2 16512 floats | probs 2048 | qu 512
#define ATTN_SMEM_FLOATS (16384 + 16512 + 2048 + 512)
__global__ __launch_bounds__(256) void attn_kernel(const int* __restrict__ distances,
                                                   const int* __restrict__ lengths,
                                                   const float* __restrict__ uvec) {
    extern __shared__ float sm[];
    float* f4K   = sm;                  // [(dv*256+key)*4]
    float* fV2   = sm + 16384;          // row p: stride 516 floats, float2 per key
    float* probs = sm + 16384 + 16512;  // [8][256]
    float* qu    = probs + 2048;        // [8][64]

    int bh = blockIdx.x;
    int b = bh >> 3, h = bh & 7;
    int q0 = blockIdx.y << 7;
    int tid = threadIdx.x;
    int lane = tid & 31, wid = tid >> 5;
    int len = lengths[b];
    const float* base = g_qkv + (size_t)(b * T) * NQKV;

    for (int i = tid; i < 4096; i += 256) {
        int key = i >> 4, dv = i & 15;
        const float* kr = base + (size_t)key * NQKV + 512 + h * 64 + dv * 4;
        float4 kv = *(const float4*)kr;
        *(float4*)&f4K[(dv * 256 + key) * 4] = kv;
        float4 vv = *(const float4*)(kr + 512);
        *(float2*)&fV2[(2 * dv) * 516 + key * 2]     = make_float2(vv.x, vv.y);
        *(float2*)&fV2[(2 * dv + 1) * 516 + key * 2] = make_float2(vv.z, vv.w);
    }
    __syncthreads();

    float u0 = uvec[h * 64 + lane];
    float u1 = uvec[h * 64 + 32 + lane];
    float* wq = qu + wid * 64;
    float* wp = probs + wid * 256;

    for (int q = q0 + wid; q < q0 + 128; q += 8) {
        const float* qrow = base + (size_t)q * NQKV + h * 64;
        wq[lane]      = qrow[lane] + u0;
        wq[lane + 32] = qrow[lane + 32] + u1;
        float srl = g_srel[(size_t)((b * H + h) * T + q) * NBUCK + lane];
        __syncwarp();

        float s[8];
        #pragma unroll
        for (int j = 0; j < 8; j++) s[j] = 0.f;
        #pragma unroll
        for (int dv = 0; dv < 16; dv++) {
            float4 qv = *(const float4*)(wq + dv * 4);
            #pragma unroll
            for (int j = 0; j < 8; j++) {
                float4 kv = *(const float4*)&f4K[(dv * 256 + lane + 32 * j) * 4];
                s[j] += qv.x * kv.x + qv.y * kv.y + qv.z * kv.z + qv.w * kv.w;
            }
        }

        const int* drow = distances + (size_t)(b * T + q) * T;
        #pragma unroll
        for (int j = 0; j < 8; j++) {
            int bk = drow[lane + 32 * j];
            float rv = __shfl_sync(0xffffffffu, srl, bk & 31);
            rv = (bk < 32) ? rv : 0.f;
            float sv = s[j] + rv;
            if (lane + 32 * j >= len) sv = -1e30f;
            s[j] = sv;
        }

        float mx = s[0];
        #pragma unroll
        for (int j = 1; j < 8; j++) mx = fmaxf(mx, s[j]);
        #pragma unroll
        for (int o = 16; o; o >>= 1) mx = fmaxf(mx, __shfl_xor_sync(0xffffffffu, mx, o));
        float e[8], sum = 0.f;
        #pragma unroll
        for (int j = 0; j < 8; j++) { e[j] = __expf(s[j] - mx); sum += e[j]; }
        #pragma unroll
        for (int o = 16; o; o >>= 1) sum += __shfl_xor_sync(0xffffffffu, sum, o);
        float inv = 1.0f / sum;
        #pragma unroll
        for (int j = 0; j < 8; j++) wp[lane + 32 * j] = e[j] * inv;
        __syncwarp();

        float a0 = 0.f, a1 = 0.f;
        const float* vrow = &fV2[lane * 516];
        #pragma unroll 4
        for (int k4 = 0; k4 < 64; k4++) {
            float4 pr = *(const float4*)&wp[k4 * 4];
            float4 va = *(const float4*)&vrow[k4 * 8];
            float4 vb = *(const float4*)&vrow[k4 * 8 + 4];
            a0 += pr.x * va.x + pr.y * va.z + pr.z * vb.x + pr.w * vb.z;
            a1 += pr.x * va.y + pr.y * va.w + pr.z * vb.y + pr.w * vb.w;
        }
        *(__nv_bfloat162*)&g_ctxb[(size_t)(b * T + q) * D + h * 64 + 2 * lane] =
            __floats2bfloat162_rn(a0, a1);
        __syncwarp();
    }
}

// ---------------- final LN + transpose (B,T,D) -> (T,B,D) ------------------
__global__ __launch_bounds__(128) void final_kernel(const float* __restrict__ gam,
                                                    const float* __restrict__ bet,
                                                    float* __restrict__ out) {
    __shared__ float sc[32];
    int tok = blockIdx.x;
    int b = tok / T, t = tok % T;
    int tid = threadIdx.x;
    const float4 vv = ((const float4*)(g_x + tok * D))[tid];
    float s = vv.x + vv.y + vv.z + vv.w;
    float mean = blkSum(s, sc) * (1.0f / D);
    float dx = vv.x - mean, dy = vv.y - mean, dz = vv.z - mean, dw = vv.w - mean;
    float sq = dx * dx + dy * dy + dz * dz + dw * dw;
    float var = blkSum(sq, sc) * (1.0f / D);
    float inv = rsqrtf(var + 1e-6f);
    float4 gv = ((const float4*)gam)[tid];
    float4 bv = ((const float4*)bet)[tid];
    float4 o;
    o.x = dx * inv * gv.x + bv.x;
    o.y = dy * inv * gv.y + bv.y;
    o.z = dz * inv * gv.z + bv.z;
    o.w = dw * inv * gv.w + bv.w;
    ((float4*)(out + ((t * B) + b) * D))[tid] = o;
}

// ---------------- host ----------------
extern "C" void kernel_launch(void* const* d_in, const int* in_sizes, int n_in,
                              void* d_out, int out_size) {
    const float* src       = (const float*)d_in[0];
    const int*   lengths   = (const int*)  d_in[1];
    const int*   distances = (const int*)  d_in[2];
    const float* u         = (const float*)d_in[3];
    const float* v         = (const float*)d_in[4];
    const float* ln1_g     = (const float*)d_in[5];
    const float* ln1_b     = (const float*)d_in[6];
    const float* Wq        = (const float*)d_in[7];
    const float* Wk        = (const float*)d_in[8];
    const float* Wv        = (const float*)d_in[9];
    const float* Wo        = (const float*)d_in[10];
    const float* bq        = (const float*)d_in[11];
    const float* bk        = (const float*)d_in[12];
    const float* bv        = (const float*)d_in[13];
    const float* bo        = (const float*)d_in[14];
    const float* rel_table = (const float*)d_in[15];
    const float* ffn_ln_g  = (const float*)d_in[16];
    const float* ffn_ln_b  = (const float*)d_in[17];
    const float* W1        = (const float*)d_in[18];
    const float* b1        = (const float*)d_in[19];
    const float* W2        = (const float*)d_in[20];
    const float* b2        = (const float*)d_in[21];
    const float* fin_g     = (const float*)d_in[22];
    const float* fin_b     = (const float*)d_in[23];
    float* out = (float*)d_out;

    float *px, *pout, *pqkv, *pbqkv;
    __nv_bfloat16 *phb, *pctxb, *phidb, *pwbf;
    cudaGetSymbolAddress((void**)&px,    g_x);
    cudaGetSymbolAddress((void**)&pout,  g_out);
    cudaGetSymbolAddress((void**)&pqkv,  g_qkv);
    cudaGetSymbolAddress((void**)&pbqkv, g_bqkv);
    cudaGetSymbolAddress((void**)&phb,   g_hb);
    cudaGetSymbolAddress((void**)&pctxb, g_ctxb);
    cudaGetSymbolAddress((void**)&phidb, g_hidb);
    cudaGetSymbolAddress((void**)&pwbf,  g_wbf);

    size_t attn_smem = (size_t)ATTN_SMEM_FLOATS * sizeof(float);
    cudaFuncSetAttribute(attn_kernel, cudaFuncAttributeMaxDynamicSharedMemorySize, (int)attn_smem);
    cudaFuncSetAttribute(gemm_tc_kernel, cudaFuncAttributeMaxDynamicSharedMemorySize, GEMM_SMEM);

    // weight conversions
    {
        int nqkv4 = NL * NQKV * D / 4;
        qkvw_kernel<<<(nqkv4 + 255) / 256, 256>>>(Wq, Wk, Wv, pwbf + QKVW_OFF);
        bqkv_kernel<<<(NL * NQKV + 255) / 256, 256>>>(bq, bk, bv, pbqkv);
        int no4 = NL * D * D / 4;
        int nf4 = NL * DFF * D / 4;
        f2bf4_kernel<<<(no4 + 255) / 256, 256>>>(Wo, pwbf + WO_OFF, no4);
        f2bf4_kernel<<<(nf4 + 255) / 256, 256>>>(W1, pwbf + W1_OFF, nf4);
        f2bf4_kernel<<<(nf4 + 255) / 256, 256>>>(W2, pwbf + W2_OFF, nf4);
    }

    embed_kernel<<<(MTOK * D + 255) / 256, 256>>>(src);

    const float qscale = 1.0f / sqrtf((float)DH);
    for (int l = 0; l < NL; l++) {
        ln_kernel<<<MTOK, 128>>>(px, phb, ln1_g + l * D, ln1_b + l * D);

        // fused QKV: [2048,1536] = hb @ Wqkv^T ; scale only first 512 cols
        gemm_tc_kernel<<<dim3(NQKV/64, MTOK/128), 256, GEMM_SMEM>>>(
            phb, pwbf + QKVW_OFF + (size_t)l * NQKV * D, pbqkv + l * NQKV, nullptr,
            pqkv, nullptr, MTOK, NQKV, D, qscale, 512, 0);

        srel_kernel<<<B * H * T, 64>>>(v, rel_table + (size_t)l * NBUCK * D);

        attn_kernel<<<dim3(B * H, 2), 256, attn_smem>>>(distances, lengths, u);

        gemm_tc_kernel<<<dim3(D/64, MTOK/128), 256, GEMM_SMEM>>>(
            pctxb, pwbf + WO_OFF + (size_t)l * D * D, bo + l * D, px,
            pout, nullptr, MTOK, D, D, 1.0f, D, 0);

        ln_kernel<<<MTOK, 128>>>(pout, phb, ffn_ln_g + l * D, ffn_ln_b + l * D);

        gemm_tc_kernel<<<dim3(DFF/64, MTOK/128), 256, GEMM_SMEM>>>(
            phb, pwbf + W1_OFF + (size_t)l * DFF * D, b1 + l * DFF, nullptr,
            nullptr, phidb, MTOK, DFF, D, 1.0f, DFF, 1);

        gemm_tc_kernel<<<dim3(D/64, MTOK/128), 256, GEMM_SMEM>>>(
            phidb, pwbf + W2_OFF + (size_t)l * DFF * D, b2 + l * D, pout,
            px, nullptr, MTOK, D, DFF, 1.0f, D, 0);
    }

    final_kernel<<<MTOK, 128>>>(fin_g, fin_b, out);
}

// round 5
// speedup vs baseline: 6.7665x; 2.4328x over previous
#include <cuda_runtime.h>
#include <cuda_bf16.h>
#include <math.h>

#define NL 4
#define D 512
#define H 8
#define DFF 2048
#define T 256
#define B 8
#define NBUCK 33
#define DH 64
#define MTOK (B*T)   // 2048
#define NQKV 1536

// bf16 weight buffer offsets (elements)
#define QKVW_OFF 0
#define WO_OFF   (NL*NQKV*D)
#define W1_OFF   (WO_OFF + NL*D*D)
#define W2_OFF   (W1_OFF + NL*DFF*D)
#define WTOT     (W2_OFF + NL*D*DFF)

// prep granule counts (float4 granules)
#define QKV4 (NL*NQKV*D/4)
#define WO4  (NL*D*D/4)
#define WFF4 (NL*DFF*D/4)

// ---------------- scratch (device globals; no allocation allowed) ----------
__device__ float g_x[MTOK*D];
__device__ float g_out[MTOK*D];
__device__ float g_qkv[MTOK*NQKV];
__device__ float g_bqkv[NL*NQKV];
__device__ __nv_bfloat16 g_hb[MTOK*D];
__device__ __nv_bfloat16 g_ctxb[MTOK*D];
__device__ __nv_bfloat16 g_hidb[MTOK*DFF];
__device__ __nv_bfloat16 g_wbf[WTOT];

// ---------------- reductions ----------------
__device__ __forceinline__ float blkSum(float v, float* sc) {
    __syncthreads();
    int tid = threadIdx.x, lane = tid & 31, w = tid >> 5, nw = blockDim.x >> 5;
    #pragma unroll
    for (int o = 16; o; o >>= 1) v += __shfl_xor_sync(0xffffffffu, v, o);
    if (lane == 0) sc[w] = v;
    __syncthreads();
    if (tid == 0) { float t = 0.f; for (int i = 0; i < nw; i++) t += sc[i]; sc[0] = t; }
    __syncthreads();
    return sc[0];
}

// ---------------- merged weight prep ---------------------------------------
__global__ void prep_w(const float* __restrict__ Wq, const float* __restrict__ Wk,
                       const float* __restrict__ Wv, const float* __restrict__ Wo,
                       const float* __restrict__ W1, const float* __restrict__ W2) {
    int i = blockIdx.x * blockDim.x + threadIdx.x;
    const float* src;
    __nv_bfloat16* dst;
    if (i < QKV4) {
        int e = i * 4;
        int l = e / (NQKV*D);
        int rem = e - l * (NQKV*D);
        int r = rem / D;
        int c = rem - r * D;
        const float* s = (r < 512) ? Wq : (r < 1024) ? Wk : Wv;
        float4 v = *(const float4*)(s + (size_t)l*D*D + (size_t)(r & 511)*D + c);
        __nv_bfloat162* o = (__nv_bfloat162*)(g_wbf + QKVW_OFF + e);
        o[0] = __floats2bfloat162_rn(v.x, v.y);
        o[1] = __floats2bfloat162_rn(v.z, v.w);
        return;
    } else if (i < QKV4 + WO4) {
        int j = i - QKV4; src = Wo; dst = g_wbf + WO_OFF + (size_t)j*4;
        float4 v = ((const float4*)src)[j];
        ((__nv_bfloat162*)dst)[0] = __floats2bfloat162_rn(v.x, v.y);
        ((__nv_bfloat162*)dst)[1] = __floats2bfloat162_rn(v.z, v.w);
        return;
    } else if (i < QKV4 + WO4 + WFF4) {
        int j = i - QKV4 - WO4; src = W1; dst = g_wbf + W1_OFF + (size_t)j*4;
        float4 v = ((const float4*)src)[j];
        ((__nv_bfloat162*)dst)[0] = __floats2bfloat162_rn(v.x, v.y);
        ((__nv_bfloat162*)dst)[1] = __floats2bfloat162_rn(v.z, v.w);
        return;
    } else if (i < QKV4 + WO4 + 2*WFF4) {
        int j = i - QKV4 - WO4 - WFF4; src = W2; dst = g_wbf + W2_OFF + (size_t)j*4;
        float4 v = ((const float4*)src)[j];
        ((__nv_bfloat162*)dst)[0] = __floats2bfloat162_rn(v.x, v.y);
        ((__nv_bfloat162*)dst)[1] = __floats2bfloat162_rn(v.z, v.w);
        return;
    }
}

__global__ void bqkv_kernel(const float* __restrict__ bq, const float* __restrict__ bk,
                            const float* __restrict__ bv) {
    int i = blockIdx.x * blockDim.x + threadIdx.x;
    if (i >= NL*NQKV) return;
    int l = i / NQKV, n = i - l*NQKV;
    float v = (n < 512) ? bq[l*D + n] : (n < 1024) ? bk[l*D + n - 512] : bv[l*D + n - 1024];
    g_bqkv[i] = v;
}

// ---------------- embedding ------------------------------------------------
__global__ void embed_kernel(const float* __restrict__ src) {
    int i = blockIdx.x * blockDim.x + threadIdx.x;
    if (i >= MTOK * D) return;
    int d = i & (D - 1);
    int t = (i / D) & (T - 1);
    int b = i / (D * T);
    float ang = (float)t * expf(-(float)(d & ~1) * (logf(10000.0f) / (float)D));
    float pe = (d & 1) ? cosf(ang) : sinf(ang);
    g_x[i] = src[((t * B) + b) * D + d] * sqrtf((float)D) + pe;
}

// ---------------- layernorm -> bf16 ----------------------------------------
__global__ __launch_bounds__(128) void ln_kernel(const float* __restrict__ in,
                                                 __nv_bfloat16* __restrict__ out,
                                                 const float* __restrict__ gam,
                                                 const float* __restrict__ bet) {
    __shared__ float sc[32];
    int tok = blockIdx.x;
    int tid = threadIdx.x;
    const float4 vv = ((const float4*)(in + tok * D))[tid];
    float s = vv.x + vv.y + vv.z + vv.w;
    float mean = blkSum(s, sc) * (1.0f / D);
    float dx = vv.x - mean, dy = vv.y - mean, dz = vv.z - mean, dw = vv.w - mean;
    float sq = dx * dx + dy * dy + dz * dz + dw * dw;
    float var = blkSum(sq, sc) * (1.0f / D);
    float inv = rsqrtf(var + 1e-6f);
    float4 gv = ((const float4*)gam)[tid];
    float4 bv = ((const float4*)bet)[tid];
    __nv_bfloat162* o2 = (__nv_bfloat162*)(out + tok * D);
    o2[2*tid]   = __floats2bfloat162_rn(dx * inv * gv.x + bv.x, dy * inv * gv.y + bv.y);
    o2[2*tid+1] = __floats2bfloat162_rn(dz * inv * gv.z + bv.z, dw * inv * gv.w + bv.w);
}

// ---------------- mma helpers ----------------------------------------------
__device__ __forceinline__ void mma_bf16(float* d, const unsigned* a, unsigned b0, unsigned b1) {
    asm volatile("mma.sync.aligned.m16n8k16.row.col.f32.bf16.bf16.f32 "
        "{%0,%1,%2,%3},{%4,%5,%6,%7},{%8,%9},{%0,%1,%2,%3};\n"
        : "+f"(d[0]), "+f"(d[1]), "+f"(d[2]), "+f"(d[3])
        : "r"(a[0]), "r"(a[1]), "r"(a[2]), "r"(a[3]), "r"(b0), "r"(b1));
}
__device__ __forceinline__ void ldsm4(unsigned* r, unsigned addr) {
    asm volatile("ldmatrix.sync.aligned.m8n8.x4.shared.b16 {%0,%1,%2,%3},[%4];\n"
        : "=r"(r[0]), "=r"(r[1]), "=r"(r[2]), "=r"(r[3]) : "r"(addr));
}
__device__ __forceinline__ void cp16(unsigned dst, const void* src) {
    asm volatile("cp.async.cg.shared.global [%0], [%1], 16;\n" :: "r"(dst), "l"(src));
}
__device__ __forceinline__ void cp_commit() { asm volatile("cp.async.commit_group;\n"); }
__device__ __forceinline__ void cp_wait0() { asm volatile("cp.async.wait_group 0;\n"); }
__device__ __forceinline__ unsigned packbf(float x, float y) {
    __nv_bfloat162 t = __floats2bfloat162_rn(x, y);
    return *(unsigned*)&t;
}

// ---------------- tensor-core GEMM with cp.async 2-stage pipeline ----------
#define GP 72
#define GEMM_SMEM ((2*128*GP + 2*64*GP) * 2)

__global__ __launch_bounds__(256) void gemm_tc_kernel(
    const __nv_bfloat16* __restrict__ A, const __nv_bfloat16* __restrict__ W,
    const float* __restrict__ bias, const float* __restrict__ resid,
    float* __restrict__ Cf, __nv_bfloat16* __restrict__ Cb,
    int M, int N, int K, float scale, int n_lo, int relu)
{
    extern __shared__ __nv_bfloat16 smg[];
    __nv_bfloat16* As = smg;
    __nv_bfloat16* Bs = smg + 2*128*GP;
    int tid = threadIdx.x;
    int lane = tid & 31, wid = tid >> 5;
    int wm = wid & 3, wn = wid >> 2;
    int m0 = blockIdx.y << 7, n0 = blockIdx.x << 6;

    int a_row = (wm << 5) + (lane & 15);
    int a_koff = (lane >> 4) << 3;
    int b_row = (wn << 5) + (lane & 7) + ((lane >> 4) << 3);
    int b_koff = ((lane >> 3) & 1) << 3;
    unsigned As_base = (unsigned)__cvta_generic_to_shared(As);
    unsigned Bs_base = (unsigned)__cvta_generic_to_shared(Bs);

    float acc[2][4][4];
    #pragma unroll
    for (int i = 0; i < 2; i++)
        #pragma unroll
        for (int j = 0; j < 4; j++)
            #pragma unroll
            for (int r = 0; r < 4; r++) acc[i][j][r] = 0.f;

    const int KT = K >> 6;
    int ca_row[4], ca_kc[4], cb_row[2], cb_kc[2];
    #pragma unroll
    for (int i = 0; i < 4; i++) { int c = tid + (i << 8); ca_row[i] = c >> 3; ca_kc[i] = (c & 7) << 3; }
    #pragma unroll
    for (int i = 0; i < 2; i++) { int c = tid + (i << 8); cb_row[i] = c >> 3; cb_kc[i] = (c & 7) << 3; }

    const __nv_bfloat16* Ag = A + (size_t)m0 * K;
    const __nv_bfloat16* Wg = W + (size_t)n0 * K;

    auto issue = [&](int kt, int s) {
        const __nv_bfloat16* a = Ag + (kt << 6);
        const __nv_bfloat16* w = Wg + (kt << 6);
        unsigned sa = As_base + (unsigned)((s * 128 * GP) << 1);
        unsigned sb = Bs_base + (unsigned)((s * 64 * GP) << 1);
        #pragma unroll
        for (int i = 0; i < 4; i++)
            cp16(sa + (unsigned)((ca_row[i] * GP + ca_kc[i]) << 1), a + (size_t)ca_row[i] * K + ca_kc[i]);
        #pragma unroll
        for (int i = 0; i < 2; i++)
            cp16(sb + (unsigned)((cb_row[i] * GP + cb_kc[i]) << 1), w + (size_t)cb_row[i] * K + cb_kc[i]);
        cp_commit();
    };

    issue(0, 0);
    for (int kt = 0; kt < KT; kt++) {
        int s = kt & 1;
        cp_wait0();
        __syncthreads();
        if (kt + 1 < KT) issue(kt + 1, s ^ 1);
        unsigned sa = As_base + (unsigned)((s * 128 * GP) << 1);
        unsigned sb = Bs_base + (unsigned)((s * 64 * GP) << 1);
        #pragma unroll
        for (int st = 0; st < 4; st++) {
            unsigned av[2][4], bv[2][4];
            unsigned abase = sa + (unsigned)((a_row * GP + (st << 4) + a_koff) << 1);
            unsigned bbase = sb + (unsigned)((b_row * GP + (st << 4) + b_koff) << 1);
            ldsm4(av[0], abase);
            ldsm4(av[1], abase + (16 * GP * 2));
            ldsm4(bv[0], bbase);
            ldsm4(bv[1], bbase + (16 * GP * 2));
            #pragma unroll
            for (int i = 0; i < 2; i++)
                #pragma unroll
                for (int j = 0; j < 2; j++) {
                    mma_bf16(acc[i][2*j],   av[i], bv[j][0], bv[j][1]);
                    mma_bf16(acc[i][2*j+1], av[i], bv[j][2], bv[j][3]);
                }
        }
        __syncthreads();
    }

    float sc = (n0 < n_lo) ? scale : 1.0f;
    int rbase = m0 + (wm << 5) + (lane >> 2);
    int cbase = n0 + (wn << 5) + ((lane & 3) << 1);
    #pragma unroll
    for (int i = 0; i < 2; i++) {
        #pragma unroll
        for (int j = 0; j < 4; j++) {
            int r0 = rbase + (i << 4);
            int cc = cbase + (j << 3);
            float2 bb = *(const float2*)&bias[cc];
            float o0 = (acc[i][j][0] + bb.x) * sc;
            float o1 = (acc[i][j][1] + bb.y) * sc;
            float o2 = (acc[i][j][2] + bb.x) * sc;
            float o3 = (acc[i][j][3] + bb.y) * sc;
            if (relu) {
                o0 = fmaxf(o0, 0.f); o1 = fmaxf(o1, 0.f);
                o2 = fmaxf(o2, 0.f); o3 = fmaxf(o3, 0.f);
            }
            if (resid) {
                float2 ra = *(const float2*)&resid[(size_t)r0 * N + cc];
                float2 rb = *(const float2*)&resid[(size_t)(r0 + 8) * N + cc];
                o0 += ra.x; o1 += ra.y; o2 += rb.x; o3 += rb.y;
            }
            if (Cf) {
                *(float2*)&Cf[(size_t)r0 * N + cc] = make_float2(o0, o1);
                *(float2*)&Cf[(size_t)(r0 + 8) * N + cc] = make_float2(o2, o3);
            }
            if (Cb) {
                *(__nv_bfloat162*)&Cb[(size_t)r0 * N + cc] = __floats2bfloat162_rn(o0, o1);
                *(__nv_bfloat162*)&Cb[(size_t)(r0 + 8) * N + cc] = __floats2bfloat162_rn(o2, o3);
            }
        }
    }
}

// ---------------- tensor-core flash attention (+ fused srel) ---------------
// per block: (b,h), 128 queries. 8 warps, 16 queries per warp.
#define KS 72    // Ksm stride (bf16)
#define VS 264   // Vtsm stride (bf16)
#define QS 72    // Qsm stride (bf16)
#define ATTN_SMEM_BYTES ((256*KS + 64*VS + 128*QS)*2 + (33*65 + 128*36)*4)

__global__ __launch_bounds__(256) void attn_tc_kernel(const int* __restrict__ distances,
                                                      const int* __restrict__ lengths,
                                                      const float* __restrict__ uvec,
                                                      const float* __restrict__ vvec,
                                                      const float* __restrict__ rel_table) {
    extern __shared__ char smraw[];
    __nv_bfloat16* Ksm  = (__nv_bfloat16*)smraw;          // [256][KS]
    __nv_bfloat16* Vtsm = Ksm + 256*KS;                   // [64][VS]  (transposed V)
    __nv_bfloat16* Qsm  = Vtsm + 64*VS;                   // [128][QS] (q + u, bf16)
    float* relsm  = (float*)(Qsm + 128*QS);               // [33][65]
    float* srelsm = relsm + 33*65;                        // [128][36]

    int bh = blockIdx.x;
    int b = bh >> 3, h = bh & 7;
    int q0 = blockIdx.y << 7;
    int tid = threadIdx.x, lane = tid & 31, wid = tid >> 5;
    int len = lengths[b];
    int bT = b * T;
    const float* base = g_qkv + (size_t)bT * NQKV;

    // K: fp32 -> bf16, row = key
    for (int i = tid; i < 256*32; i += 256) {
        int key = i >> 5, dp = (i & 31) << 1;
        float2 kv = *(const float2*)(base + (size_t)key*NQKV + 512 + h*64 + dp);
        *(__nv_bfloat162*)&Ksm[key*KS + dp] = __floats2bfloat162_rn(kv.x, kv.y);
    }
    // V transposed: Vt[dh][key]
    for (int i = tid; i < 64*128; i += 256) {
        int dh = i >> 7, kp = (i & 127) << 1;
        float v0 = base[(size_t)kp*NQKV + 1024 + h*64 + dh];
        float v1 = base[(size_t)(kp+1)*NQKV + 1024 + h*64 + dh];
        *(__nv_bfloat162*)&Vtsm[dh*VS + kp] = __floats2bfloat162_rn(v0, v1);
    }
    // rel table (this head)
    for (int i = tid; i < 33*64; i += 256) {
        int bk = i >> 6, d2 = i & 63;
        relsm[bk*65 + d2] = rel_table[bk*D + h*64 + d2];
    }
    // Q + u -> bf16
    for (int i = tid; i < 128*32; i += 256) {
        int q = i >> 5, dp = (i & 31) << 1;
        float2 qv = *(const float2*)(base + (size_t)(q0+q)*NQKV + h*64 + dp);
        float2 uu = *(const float2*)(uvec + h*64 + dp);
        *(__nv_bfloat162*)&Qsm[q*QS + dp] = __floats2bfloat162_rn(qv.x+uu.x, qv.y+uu.y);
    }
    __syncthreads();

    // srel: warp -> its 16 queries; lane = bucket (bucket 32 == 0)
    int wq = wid << 4;
    for (int qi = 0; qi < 16; qi++) {
        int q = q0 + wq + qi;
        float qv0 = base[(size_t)q*NQKV + h*64 + lane]      + vvec[h*64 + lane];
        float qv1 = base[(size_t)q*NQKV + h*64 + 32 + lane] + vvec[h*64 + 32 + lane];
        const float* rrow = relsm + lane*65;
        float acc = 0.f;
        #pragma unroll
        for (int d2 = 0; d2 < 32; d2++)
            acc += __shfl_sync(0xffffffffu, qv0, d2) * rrow[d2];
        #pragma unroll
        for (int d2 = 0; d2 < 32; d2++)
            acc += __shfl_sync(0xffffffffu, qv1, d2) * rrow[32 + d2];
        srelsm[(wq+qi)*36 + lane] = acc;
        if (lane == 0) srelsm[(wq+qi)*36 + 32] = 0.f;
    }
    __syncwarp();

    unsigned Ks_base = (unsigned)__cvta_generic_to_shared(Ksm);
    unsigned Vs_base = (unsigned)__cvta_generic_to_shared(Vtsm);
    unsigned Qs_base = (unsigned)__cvta_generic_to_shared(Qsm);

    int a_row_q = wq + (lane & 15);
    int a_koff = (lane >> 4) << 3;
    int b_nrow = (lane & 7) + ((lane >> 4) << 3);
    int b_koff = ((lane >> 3) & 1) << 3;
    int r_lo = lane >> 2;
    int c4 = (lane & 3) << 1;

    float m_i0 = -1e30f, m_i1 = -1e30f, l_i0 = 0.f, l_i1 = 0.f;
    float ctx[8][4];
    #pragma unroll
    for (int t = 0; t < 8; t++)
        #pragma unroll
        for (int r = 0; r < 4; r++) ctx[t][r] = 0.f;

    for (int kc = 0; kc < 2; kc++) {
        int kbase = kc << 7;
        float S[16][4];
        #pragma unroll
        for (int j = 0; j < 16; j++)
            #pragma unroll
            for (int r = 0; r < 4; r++) S[j][r] = 0.f;

        #pragma unroll
        for (int st = 0; st < 4; st++) {
            unsigned av[4];
            ldsm4(av, Qs_base + (unsigned)((a_row_q*QS + (st << 4) + a_koff) << 1));
            #pragma unroll
            for (int j2 = 0; j2 < 8; j2++) {
                unsigned bv[4];
                ldsm4(bv, Ks_base + (unsigned)(((kbase + (j2 << 4) + b_nrow)*KS + (st << 4) + b_koff) << 1));
                mma_bf16(S[2*j2],   av, bv[0], bv[1]);
                mma_bf16(S[2*j2+1], av, bv[2], bv[3]);
            }
        }

        // add rel term, mask, row max
        int qrow = wq + r_lo;
        const int* drow0 = distances + (size_t)(bT + q0 + qrow) * T + kbase + c4;
        const int* drow1 = drow0 + 8 * T;
        const float* sr0 = srelsm + qrow * 36;
        const float* sr1 = sr0 + 8 * 36;
        float mn0 = m_i0, mn1 = m_i1;
        #pragma unroll
        for (int j = 0; j < 16; j++) {
            int k = kbase + (j << 3) + c4;
            float s0 = S[j][0] + sr0[drow0[j*8]];
            float s1 = S[j][1] + sr0[drow0[j*8 + 1]];
            float s2 = S[j][2] + sr1[drow1[j*8]];
            float s3 = S[j][3] + sr1[drow1[j*8 + 1]];
            bool v0 = k < len, v1 = (k + 1) < len;
            s0 = v0 ? s0 : -1e30f; s1 = v1 ? s1 : -1e30f;
            s2 = v0 ? s2 : -1e30f; s3 = v1 ? s3 : -1e30f;
            S[j][0] = s0; S[j][1] = s1; S[j][2] = s2; S[j][3] = s3;
            mn0 = fmaxf(mn0, fmaxf(s0, s1));
            mn1 = fmaxf(mn1, fmaxf(s2, s3));
        }
        mn0 = fmaxf(mn0, __shfl_xor_sync(0xffffffffu, mn0, 1));
        mn0 = fmaxf(mn0, __shfl_xor_sync(0xffffffffu, mn0, 2));
        mn1 = fmaxf(mn1, __shfl_xor_sync(0xffffffffu, mn1, 1));
        mn1 = fmaxf(mn1, __shfl_xor_sync(0xffffffffu, mn1, 2));

        float ps0 = __expf(m_i0 - mn0), ps1 = __expf(m_i1 - mn1);
        float ls0 = 0.f, ls1 = 0.f;
        #pragma unroll
        for (int j = 0; j < 16; j++) {
            S[j][0] = __expf(S[j][0] - mn0);
            S[j][1] = __expf(S[j][1] - mn0);
            S[j][2] = __expf(S[j][2] - mn1);
            S[j][3] = __expf(S[j][3] - mn1);
            ls0 += S[j][0] + S[j][1];
            ls1 += S[j][2] + S[j][3];
        }
        ls0 += __shfl_xor_sync(0xffffffffu, ls0, 1);
        ls0 += __shfl_xor_sync(0xffffffffu, ls0, 2);
        ls1 += __shfl_xor_sync(0xffffffffu, ls1, 1);
        ls1 += __shfl_xor_sync(0xffffffffu, ls1, 2);
        l_i0 = l_i0 * ps0 + ls0;
        l_i1 = l_i1 * ps1 + ls1;
        m_i0 = mn0; m_i1 = mn1;
        #pragma unroll
        for (int t = 0; t < 8; t++) {
            ctx[t][0] *= ps0; ctx[t][1] *= ps0;
            ctx[t][2] *= ps1; ctx[t][3] *= ps1;
        }

        // PV: P packed register-direct into A fragments
        #pragma unroll
        for (int t = 0; t < 8; t++) {
            unsigned aP[4];
            aP[0] = packbf(S[2*t][0],   S[2*t][1]);
            aP[1] = packbf(S[2*t][2],   S[2*t][3]);
            aP[2] = packbf(S[2*t+1][0], S[2*t+1][1]);
            aP[3] = packbf(S[2*t+1][2], S[2*t+1][3]);
            #pragma unroll
            for (int v4 = 0; v4 < 4; v4++) {
                unsigned bv[4];
                ldsm4(bv, Vs_base + (unsigned)((((v4 << 4) + b_nrow)*VS + kbase + (t << 4) + b_koff) << 1));
                mma_bf16(ctx[2*v4],   aP, bv[0], bv[1]);
                mma_bf16(ctx[2*v4+1], aP, bv[2], bv[3]);
            }
        }
    }

    float inv0 = 1.0f / l_i0, inv1 = 1.0f / l_i1;
    int qa = bT + q0 + wq + r_lo;
    #pragma unroll
    for (int t = 0; t < 8; t++) {
        int dh = ((t >> 1) << 4) + ((t & 1) << 3) + c4;
        *(__nv_bfloat162*)&g_ctxb[(size_t)qa * D + h*64 + dh] =
            __floats2bfloat162_rn(ctx[t][0] * inv0, ctx[t][1] * inv0);
        *(__nv_bfloat162*)&g_ctxb[(size_t)(qa + 8) * D + h*64 + dh] =
            __floats2bfloat162_rn(ctx[t][2] * inv1, ctx[t][3] * inv1);
    }
}

// ---------------- final LN + transpose (B,T,D) -> (T,B,D) ------------------
__global__ __launch_bounds__(128) void final_kernel(const float* __restrict__ gam,
                                                    const float* __restrict__ bet,
                                                    float* __restrict__ out) {
    __shared__ float sc[32];
    int tok = blockIdx.x;
    int b = tok / T, t = tok % T;
    int tid = threadIdx.x;
    const float4 vv = ((const float4*)(g_x + tok * D))[tid];
    float s = vv.x + vv.y + vv.z + vv.w;
    float mean = blkSum(s, sc) * (1.0f / D);
    float dx = vv.x - mean, dy = vv.y - mean, dz = vv.z - mean, dw = vv.w - mean;
    float sq = dx * dx + dy * dy + dz * dz + dw * dw;
    float var = blkSum(sq, sc) * (1.0f / D);
    float inv = rsqrtf(var + 1e-6f);
    float4 gv = ((const float4*)gam)[tid];
    float4 bv = ((const float4*)bet)[tid];
    float4 o;
    o.x = dx * inv * gv.x + bv.x;
    o.y = dy * inv * gv.y + bv.y;
    o.z = dz * inv * gv.z + bv.z;
    o.w = dw * inv * gv.w + bv.w;
    ((float4*)(out + ((t * B) + b) * D))[tid] = o;
}

// ---------------- host ----------------
extern "C" void kernel_launch(void* const* d_in, const int* in_sizes, int n_in,
                              void* d_out, int out_size) {
    const float* src       = (const float*)d_in[0];
    const int*   lengths   = (const int*)  d_in[1];
    const int*   distances = (const int*)  d_in[2];
    const float* u         = (const float*)d_in[3];
    const float* v         = (const float*)d_in[4];
    const float* ln1_g     = (const float*)d_in[5];
    const float* ln1_b     = (const float*)d_in[6];
    const float* Wq        = (const float*)d_in[7];
    const float* Wk        = (const float*)d_in[8];
    const float* Wv        = (const float*)d_in[9];
    const float* Wo        = (const float*)d_in[10];
    const float* bq        = (const float*)d_in[11];
    const float* bk        = (const float*)d_in[12];
    const float* bv        = (const float*)d_in[13];
    const float* bo        = (const float*)d_in[14];
    const float* rel_table = (const float*)d_in[15];
    const float* ffn_ln_g  = (const float*)d_in[16];
    const float* ffn_ln_b  = (const float*)d_in[17];
    const float* W1        = (const float*)d_in[18];
    const float* b1        = (const float*)d_in[19];
    const float* W2        = (const float*)d_in[20];
    const float* b2        = (const float*)d_in[21];
    const float* fin_g     = (const float*)d_in[22];
    const float* fin_b     = (const float*)d_in[23];
    float* out = (float*)d_out;

    float *px, *pout, *pqkv, *pbqkv;
    __nv_bfloat16 *phb, *pctxb, *phidb, *pwbf;
    cudaGetSymbolAddress((void**)&px,    g_x);
    cudaGetSymbolAddress((void**)&pout,  g_out);
    cudaGetSymbolAddress((void**)&pqkv,  g_qkv);
    cudaGetSymbolAddress((void**)&pbqkv, g_bqkv);
    cudaGetSymbolAddress((void**)&phb,   g_hb);
    cudaGetSymbolAddress((void**)&pctxb, g_ctxb);
    cudaGetSymbolAddress((void**)&phidb, g_hidb);
    cudaGetSymbolAddress((void**)&pwbf,  g_wbf);

    cudaFuncSetAttribute(attn_tc_kernel, cudaFuncAttributeMaxDynamicSharedMemorySize, ATTN_SMEM_BYTES);
    cudaFuncSetAttribute(gemm_tc_kernel, cudaFuncAttributeMaxDynamicSharedMemorySize, GEMM_SMEM);

    prep_w<<<(QKV4 + WO4 + 2*WFF4) / 256, 256>>>(Wq, Wk, Wv, Wo, W1, W2);
    bqkv_kernel<<<(NL * NQKV + 255) / 256, 256>>>(bq, bk, bv);
    embed_kernel<<<(MTOK * D + 255) / 256, 256>>>(src);

    const float qscale = 1.0f / sqrtf((float)DH);
    for (int l = 0; l < NL; l++) {
        ln_kernel<<<MTOK, 128>>>(px, phb, ln1_g + l * D, ln1_b + l * D);

        gemm_tc_kernel<<<dim3(NQKV/64, MTOK/128), 256, GEMM_SMEM>>>(
            phb, pwbf + QKVW_OFF + (size_t)l * NQKV * D, pbqkv + l * NQKV, nullptr,
            pqkv, nullptr, MTOK, NQKV, D, qscale, 512, 0);

        attn_tc_kernel<<<dim3(B * H, 2), 256, ATTN_SMEM_BYTES>>>(
            distances, lengths, u, v, rel_table + (size_t)l * NBUCK * D);

        gemm_tc_kernel<<<dim3(D/64, MTOK/128), 256, GEMM_SMEM>>>(
            pctxb, pwbf + WO_OFF + (size_t)l * D * D, bo + l * D, px,
            pout, nullptr, MTOK, D, D, 1.0f, D, 0);

        ln_kernel<<<MTOK, 128>>>(pout, phb, ffn_ln_g + l * D, ffn_ln_b + l * D);

        gemm_tc_kernel<<<dim3(DFF/64, MTOK/128), 256, GEMM_SMEM>>>(
            phb, pwbf + W1_OFF + (size_t)l * DFF * D, b1 + l * DFF, nullptr,
            nullptr, phidb, MTOK, DFF, D, 1.0f, DFF, 1);

        gemm_tc_kernel<<<dim3(D/64, MTOK/128), 256, GEMM_SMEM>>>(
            phidb, pwbf + W2_OFF + (size_t)l * DFF * D, b2 + l * D, pout,
            px, nullptr, MTOK, D, DFF, 1.0f, D, 0);
    }

    final_kernel<<<MTOK, 128>>>(fin_g, fin_b, out);
}